// round 1
// baseline (speedup 1.0000x reference)
#include <cuda_runtime.h>
#include <cuda_fp16.h>
#include <cstdint>
#include <math.h>

// Problem constants (from metadata: buffers[256,64,1024] f32, transitions[256,127] i32,
// Wl[512,2560] f32, Wr[512,2560] f32, bl[2560] f32, out[256,512] f32)
#define BSZ   256      // batch
#define NLEAF 64       // leaves per batch
#define SZ    512      // hidden size
#define D2    1024     // 2*SZ (h|c)
#define GN    2560     // 5*SZ gates
#define RMAX  64       // max reduce events we support per batch

// GEMM tile config
#define BM 64
#define BN 80          // 16 hidden units * 5 gates
#define BK 32
#define ALD 40         // A smem leading dim (halfs), padded
#define BLD 34         // B smem leading dim (halfs), padded

// ---------------- device globals (scratch; no dynamic allocation) ----------------
__device__ float  g_slots[BSZ][RMAX + 1][D2];   // slot RMAX is the zero item
__device__ __half g_W[D2 * GN];                 // [k][5j+g] gate-interleaved fp16 weights
__device__ float  g_bias[GN];                   // gate-interleaved bias
__device__ int    g_lop[BSZ * RMAX];            // left operand per reduce event
__device__ int    g_rop[BSZ * RMAX];            // right operand per reduce event
__device__ int    g_nred[BSZ];                  // reduce count per batch
__device__ int    g_top[BSZ];                   // final stack-top operand

__device__ __forceinline__ float sigm(float x) { return 1.0f / (1.0f + expf(-x)); }

// ---------------- init: zero the "empty stack item" slot ----------------
__global__ void init_zero_kernel() {
    int i = blockIdx.x * blockDim.x + threadIdx.x;
    if (i < BSZ * D2) g_slots[i / D2][RMAX][i % D2] = 0.0f;
}

// ---------------- weight conversion: fp32 -> fp16, gate-interleave columns ----------------
// source col sc = g*SZ + j  ->  dest col dc = 5*j + g
__global__ void convert_w_kernel(const float* __restrict__ Wl,
                                 const float* __restrict__ Wr,
                                 const float* __restrict__ bl) {
    int i = blockIdx.x * blockDim.x + threadIdx.x;
    if (i >= D2 * GN) return;
    int k = i / GN, sc = i % GN;
    int g = sc / SZ, j = sc % SZ;
    int dc = 5 * j + g;
    float v = (k < SZ) ? Wl[k * GN + sc] : Wr[(k - SZ) * GN + sc];
    g_W[k * GN + dc] = __float2half(v);
    if (k == 0) g_bias[dc] = bl[sc];
}

// ---------------- schedule: simulate the stack symbolically, one thread per batch ----------------
// Operand encoding: v >= 0 -> g_slots[b][v]; v < 0 -> buffers row (-v-1). RMAX = zero item.
__global__ void schedule_kernel(const int* __restrict__ trans, int T) {
    int b = threadIdx.x;
    if (b >= BSZ) return;
    int trv[132];
    #pragma unroll 4
    for (int t = 0; t < T; t++) trv[t] = trans[b * T + t];

    int st[132];
    for (int i = 0; i < 132; i++) st[i] = RMAX;   // zero items
    int ptr = 0, bptr = 0, nr = 0;
    for (int t = 0; t < T; t++) {
        int tr = trv[t];
        if (tr == 0) {                                   // SHIFT
            int n = (bptr < NLEAF - 1) ? bptr : (NLEAF - 1);
            int wp = ptr; if (wp < 0) wp = 0; if (wp > 130) wp = 130;
            st[wp] = -(n + 1);
            ptr++; bptr++;
        } else if (tr == 1) {                            // REDUCE
            int lp = ptr - 2; if (lp < 0) lp = 0;
            int rp = ptr - 1; if (rp < 0) rp = 0;
            if (nr < RMAX) {
                g_lop[b * RMAX + nr] = st[lp];
                g_rop[b * RMAX + nr] = st[rp];
                st[lp] = nr;
                nr++;
            }
            ptr--;
        }                                                // SKIP: nothing
    }
    g_nred[b] = nr;
    int tp = ptr - 1; if (tp < 0) tp = 0; if (tp > 130) tp = 130;
    g_top[b] = st[tp];
}

// ---------------- mma.sync m16n8k16 fp16 -> fp32 ----------------
__device__ __forceinline__ void mma16816(float* c, uint32_t a0, uint32_t a1, uint32_t a2,
                                         uint32_t a3, uint32_t b0, uint32_t b1) {
    asm volatile(
        "mma.sync.aligned.m16n8k16.row.col.f32.f16.f16.f32 "
        "{%0,%1,%2,%3},{%4,%5,%6,%7},{%8,%9},{%0,%1,%2,%3};\n"
        : "+f"(c[0]), "+f"(c[1]), "+f"(c[2]), "+f"(c[3])
        : "r"(a0), "r"(a1), "r"(a2), "r"(a3), "r"(b0), "r"(b1));
}

// ---------------- fused reduce step: GEMM(256x2560, K=1024) + LSTM epilogue ----------------
// grid = (GN/BN=32, BSZ/BM=4), 256 threads (8 warps as 4x2 of 16x40 warp tiles)
__global__ __launch_bounds__(256) void step_kernel(const float* __restrict__ buffers, int kred) {
    __shared__ __half As[BM][ALD];
    __shared__ __half Bs[BN][BLD];
    __shared__ float  Gs[BM][BN + 1];
    __shared__ const float* lptr[BM];
    __shared__ const float* rptr[BM];
    __shared__ int valid[BM];

    int tid  = threadIdx.x;
    int warp = tid >> 5, lane = tid & 31;
    int row0 = blockIdx.y * BM;
    int col0 = blockIdx.x * BN;

    if (tid < BM) {
        int b   = row0 + tid;
        int lop = g_lop[b * RMAX + kred];
        int rop = g_rop[b * RMAX + kred];
        lptr[tid] = (lop >= 0) ? &g_slots[b][lop][0]
                               : (buffers + (size_t)b * NLEAF * D2 + (size_t)(-lop - 1) * D2);
        rptr[tid] = (rop >= 0) ? &g_slots[b][rop][0]
                               : (buffers + (size_t)b * NLEAF * D2 + (size_t)(-rop - 1) * D2);
        valid[tid] = (kred < g_nred[b]) ? 1 : 0;
    }
    // barrier + whole-block early exit if no row needs this reduce index
    if (__syncthreads_or((tid < BM) ? valid[tid] : 0) == 0) return;

    float acc[5][4];
    #pragma unroll
    for (int f = 0; f < 5; f++)
        #pragma unroll
        for (int q = 0; q < 4; q++) acc[f][q] = 0.0f;

    const int KT = D2 / BK;   // 32 k-tiles
    float    areg[8];
    uint32_t breg[5];

    auto ldg_tile = [&](int kt) {
        int  k0   = kt * BK;
        bool left = (k0 < SZ);
        int  koff = left ? k0 : (k0 - SZ);
        #pragma unroll
        for (int i = 0; i < 8; i++) {
            int e = tid + i * 256;              // 0..2047 over 64x32
            int r = e >> 5, kk = e & 31;        // coalesced in kk
            const float* base = left ? lptr[r] : rptr[r];
            areg[i] = base[koff + kk];
        }
        #pragma unroll
        for (int i = 0; i < 5; i++) {
            int e  = tid + i * 256;             // 0..1279 over 80x32 halfs as b32 pairs
            int kk = e / 40;
            int n2 = (e % 40) * 2;              // coalesced in n
            breg[i] = *reinterpret_cast<const uint32_t*>(&g_W[(k0 + kk) * GN + col0 + n2]);
        }
    };
    auto sts_tile = [&]() {
        #pragma unroll
        for (int i = 0; i < 8; i++) {
            int e = tid + i * 256;
            int r = e >> 5, kk = e & 31;
            As[r][kk] = __float2half(areg[i]);
        }
        #pragma unroll
        for (int i = 0; i < 5; i++) {
            int e  = tid + i * 256;
            int kk = e / 40;
            int n2 = (e % 40) * 2;
            __half2 h2 = *reinterpret_cast<__half2*>(&breg[i]);
            Bs[n2][kk]     = __low2half(h2);
            Bs[n2 + 1][kk] = __high2half(h2);
        }
    };

    ldg_tile(0);
    sts_tile();
    __syncthreads();

    int wr = (warp >> 1) * 16;   // warp m base
    int wc = (warp & 1) * 40;    // warp n base
    int gp = lane >> 2, t4 = lane & 3;

    for (int kt = 0; kt < KT; ++kt) {
        if (kt + 1 < KT) ldg_tile(kt + 1);   // prefetch next tile into registers
        #pragma unroll
        for (int ks = 0; ks < 2; ++ks) {
            int kb = ks * 16;
            uint32_t a0 = *(const uint32_t*)&As[wr + gp    ][kb + t4 * 2];
            uint32_t a1 = *(const uint32_t*)&As[wr + gp + 8][kb + t4 * 2];
            uint32_t a2 = *(const uint32_t*)&As[wr + gp    ][kb + t4 * 2 + 8];
            uint32_t a3 = *(const uint32_t*)&As[wr + gp + 8][kb + t4 * 2 + 8];
            #pragma unroll
            for (int f = 0; f < 5; ++f) {
                int n0 = wc + f * 8 + gp;
                uint32_t b0 = *(const uint32_t*)&Bs[n0][kb + t4 * 2];
                uint32_t b1 = *(const uint32_t*)&Bs[n0][kb + t4 * 2 + 8];
                mma16816(acc[f], a0, a1, a2, a3, b0, b1);
            }
        }
        __syncthreads();
        if (kt + 1 < KT) { sts_tile(); __syncthreads(); }
    }

    // ---- dump gate accumulators to smem ----
    #pragma unroll
    for (int f = 0; f < 5; ++f) {
        int c = wc + f * 8 + t4 * 2;
        Gs[wr + gp    ][c]     = acc[f][0];
        Gs[wr + gp    ][c + 1] = acc[f][1];
        Gs[wr + gp + 8][c]     = acc[f][2];
        Gs[wr + gp + 8][c + 1] = acc[f][3];
    }
    __syncthreads();

    // ---- LSTM epilogue: 64 rows x 16 hidden units per CTA ----
    #pragma unroll
    for (int i = 0; i < 4; i++) {
        int e  = tid + i * 256;      // 0..1023
        int r  = e >> 4;
        int jl = e & 15;
        if (!valid[r]) continue;
        int b  = row0 + r;
        int jg = col0 / 5 + jl;      // global hidden index
        int cb = jl * 5;
        float a  = Gs[r][cb + 0] + g_bias[col0 + cb + 0];
        float ii = Gs[r][cb + 1] + g_bias[col0 + cb + 1];
        float f1 = Gs[r][cb + 2] + g_bias[col0 + cb + 2];
        float f2 = Gs[r][cb + 3] + g_bias[col0 + cb + 3];
        float o  = Gs[r][cb + 4] + g_bias[col0 + cb + 4];
        float lc = lptr[r][SZ + jg];
        float rc = rptr[r][SZ + jg];
        float cc = tanhf(a) * sigm(ii) + sigm(f1) * lc + sigm(f2) * rc;
        float hh = sigm(o) * tanhf(cc);
        g_slots[b][kred][jg]      = hh;
        g_slots[b][kred][SZ + jg] = cc;
    }
}

// ---------------- final: gather h of the stack top ----------------
__global__ void final_kernel(const float* __restrict__ buffers, float* __restrict__ out) {
    int i = blockIdx.x * blockDim.x + threadIdx.x;
    if (i >= BSZ * SZ) return;
    int b = i / SZ, j = i % SZ;
    int op = g_top[b];
    const float* base = (op >= 0) ? &g_slots[b][op][0]
                                  : (buffers + (size_t)b * NLEAF * D2 + (size_t)(-op - 1) * D2);
    out[i] = base[j];
}

// ---------------- launch ----------------
extern "C" void kernel_launch(void* const* d_in, const int* in_sizes, int n_in,
                              void* d_out, int out_size) {
    const float* buffers = (const float*)d_in[0];
    const int*   trans   = (const int*)d_in[1];
    const float* Wl      = (const float*)d_in[2];
    const float* Wr      = (const float*)d_in[3];
    const float* bl      = (const float*)d_in[4];
    float*       out     = (float*)d_out;

    int T  = in_sizes[1] / BSZ;          // 127
    int RL = (T + 1) / 2;                // max reduces per batch for a well-formed run
    if (RL > RMAX) RL = RMAX;

    init_zero_kernel<<<(BSZ * D2 + 255) / 256, 256>>>();
    convert_w_kernel<<<(D2 * GN + 255) / 256, 256>>>(Wl, Wr, bl);
    schedule_kernel<<<1, 256>>>(trans, T);

    dim3 grid(GN / BN, BSZ / BM);        // (32, 4) = 128 CTAs
    for (int k = 0; k < RL; ++k)
        step_kernel<<<grid, 256>>>(buffers, k);

    final_kernel<<<(BSZ * SZ + 255) / 256, 256>>>(buffers, out);
}

// round 2
// speedup vs baseline: 1.9625x; 1.9625x over previous
#include <cuda_runtime.h>
#include <cuda_fp16.h>
#include <cstdint>
#include <math.h>

#define BSZ   256
#define NLEAF 64
#define SZ    512
#define D2    1024
#define GN    2560
#define RMAX  64
#define NSLOT 129       // 0..63 leaves, 64..127 reduce results, 128 zero item

#define BM 64
#define BN 80
#define BK 32
#define ST 4            // pipeline stages
#define AROW 80         // A smem row stride bytes (40 halfs, conflict-free for ldmatrix)
#define STAGE_A 5120    // 64*80
#define STAGE_B 6400    // 80*80
#define STAGE_BYTES 11520

// ---------------- device scratch ----------------
__device__ __half g_h[BSZ][NSLOT][SZ];        // fp16 h operands (GEMM A source)
__device__ float  g_c[BSZ][RMAX + 1][SZ];     // fp32 c (slot RMAX = zeros)
__device__ float  g_hf[BSZ][RMAX][SZ];        // fp32 h of reduce results (final output)
__device__ __half g_Wt[GN * D2];              // weights transposed [dc][k], gate-interleaved
__device__ float  g_bias[GN];
__device__ int    g_lop[BSZ * RMAX];
__device__ int    g_rop[BSZ * RMAX];
__device__ int    g_nred[BSZ];
__device__ int    g_top[BSZ];

__device__ __forceinline__ float sigm(float x) { return 1.0f / (1.0f + expf(-x)); }

// ---------------- PTX helpers ----------------
__device__ __forceinline__ void cp16(uint32_t sdst, const void* gsrc) {
    asm volatile("cp.async.cg.shared.global [%0], [%1], 16;\n" :: "r"(sdst), "l"(gsrc));
}
__device__ __forceinline__ void cp_commit() { asm volatile("cp.async.commit_group;\n" ::); }
template <int N> __device__ __forceinline__ void cp_wait() {
    asm volatile("cp.async.wait_group %0;\n" :: "n"(N));
}
__device__ __forceinline__ void ldsm4(uint32_t& r0, uint32_t& r1, uint32_t& r2, uint32_t& r3,
                                      uint32_t addr) {
    asm volatile("ldmatrix.sync.aligned.m8n8.x4.shared.b16 {%0,%1,%2,%3},[%4];\n"
                 : "=r"(r0), "=r"(r1), "=r"(r2), "=r"(r3) : "r"(addr));
}
__device__ __forceinline__ void ldsm2(uint32_t& r0, uint32_t& r1, uint32_t addr) {
    asm volatile("ldmatrix.sync.aligned.m8n8.x2.shared.b16 {%0,%1},[%2];\n"
                 : "=r"(r0), "=r"(r1) : "r"(addr));
}
__device__ __forceinline__ void mma16816(float* c, uint32_t a0, uint32_t a1, uint32_t a2,
                                         uint32_t a3, uint32_t b0, uint32_t b1) {
    asm volatile(
        "mma.sync.aligned.m16n8k16.row.col.f32.f16.f16.f32 "
        "{%0,%1,%2,%3},{%4,%5,%6,%7},{%8,%9},{%0,%1,%2,%3};\n"
        : "+f"(c[0]), "+f"(c[1]), "+f"(c[2]), "+f"(c[3])
        : "r"(a0), "r"(a1), "r"(a2), "r"(a3), "r"(b0), "r"(b1));
}

// ---------------- setup kernels ----------------
__global__ void init_zero_kernel() {
    int i = blockIdx.x * blockDim.x + threadIdx.x;
    if (i < BSZ * SZ) {
        g_h[i / SZ][NSLOT - 1][i % SZ] = __float2half(0.0f);
        g_c[i / SZ][RMAX][i % SZ]      = 0.0f;
    }
}

__global__ void leaf_convert_kernel(const float* __restrict__ buffers) {
    int i = blockIdx.x * blockDim.x + threadIdx.x;
    if (i >= BSZ * NLEAF * SZ) return;
    int b = i / (NLEAF * SZ);
    int r = (i / SZ) % NLEAF;
    int j = i % SZ;
    g_h[b][r][j] = __float2half(buffers[(size_t)b * NLEAF * D2 + (size_t)r * D2 + j]);
}

// g_Wt[dc][k], dc = 5*j + g from source col sc = g*SZ + j
__global__ void convert_w_kernel(const float* __restrict__ Wl,
                                 const float* __restrict__ Wr,
                                 const float* __restrict__ bl) {
    int i = blockIdx.x * blockDim.x + threadIdx.x;
    if (i >= GN * D2) return;
    int dc = i >> 10, k = i & 1023;
    int j = dc / 5, g = dc % 5;
    int sc = g * SZ + j;
    float v = (k < SZ) ? Wl[k * GN + sc] : Wr[(k - SZ) * GN + sc];
    g_Wt[i] = __float2half(v);
    if (k == 0) g_bias[dc] = bl[sc];
}

// one thread per batch: symbolic stack simulation
// operand encoding: 0..63 leaf row, 64..127 reduce slot, 128 zero item
__global__ void schedule_kernel(const int* __restrict__ trans, int T) {
    int b = threadIdx.x;
    if (b >= BSZ) return;
    int st[132];
    for (int i = 0; i < 132; i++) st[i] = NSLOT - 1;
    int ptr = 0, bptr = 0, nr = 0;
    for (int t = 0; t < T; t++) {
        int tr = trans[b * T + t];
        if (tr == 0) {                                   // SHIFT
            int n = (bptr < NLEAF - 1) ? bptr : (NLEAF - 1);
            int wp = ptr; if (wp < 0) wp = 0; if (wp > 130) wp = 130;
            st[wp] = n;
            ptr++; bptr++;
        } else if (tr == 1) {                            // REDUCE
            int lp = ptr - 2; if (lp < 0) lp = 0;
            int rp = ptr - 1; if (rp < 0) rp = 0;
            if (nr < RMAX) {
                g_lop[b * RMAX + nr] = st[lp];
                g_rop[b * RMAX + nr] = st[rp];
                st[lp] = 64 + nr;
                nr++;
            }
            ptr--;
        }
    }
    g_nred[b] = nr;
    int tp = ptr - 1; if (tp < 0) tp = 0; if (tp > 130) tp = 130;
    g_top[b] = st[tp];
}

// ---------------- fused reduce step ----------------
// grid (GN/BN=32, BSZ/BM=4), 256 threads, 8 warps (4m x 2n of 16x40 warp tiles)
__global__ __launch_bounds__(256) void step_kernel(const float* __restrict__ buffers, int kred) {
    __shared__ __align__(16) char smem[ST * STAGE_BYTES];     // 46080 B, reused as Gs
    __shared__ const __half* s_lh[BM];
    __shared__ const __half* s_rh[BM];
    __shared__ const float*  s_lc[BM];
    __shared__ const float*  s_rc[BM];
    __shared__ int s_valid[BM];

    int tid = threadIdx.x, warp = tid >> 5, lane = tid & 31;
    int row0 = blockIdx.y * BM, col0 = blockIdx.x * BN;

    int myvalid = 0;
    if (tid < BM) {
        int b   = row0 + tid;
        int lop = g_lop[b * RMAX + kred];
        int rop = g_rop[b * RMAX + kred];
        s_lh[tid] = &g_h[b][lop][0];
        s_rh[tid] = &g_h[b][rop][0];
        s_lc[tid] = (lop < 64)  ? (buffers + (size_t)b * NLEAF * D2 + (size_t)lop * D2 + SZ)
                  : (lop < 128) ? &g_c[b][lop - 64][0] : &g_c[b][RMAX][0];
        s_rc[tid] = (rop < 64)  ? (buffers + (size_t)b * NLEAF * D2 + (size_t)rop * D2 + SZ)
                  : (rop < 128) ? &g_c[b][rop - 64][0] : &g_c[b][RMAX][0];
        myvalid = s_valid[tid] = (kred < g_nred[b]) ? 1 : 0;
    }
    if (!__syncthreads_or(myvalid)) return;

    // per-thread fixed addresses
    uint32_t smembase = (uint32_t)__cvta_generic_to_shared(smem);
    int arow = tid >> 2, achk = tid & 3;
    const char* lsrc = (const char*)s_lh[arow] + achk * 16;
    const char* rsrc = (const char*)s_rh[arow] + achk * 16;
    uint32_t adst  = smembase + arow * AROW + achk * 16;
    const char* wbase = (const char*)g_Wt;
    const char* bsrc1 = wbase + (size_t)(col0 + (tid >> 2)) * 2048 + (tid & 3) * 16;
    const char* bsrc2 = wbase + (size_t)(col0 + 64 + (tid >> 2)) * 2048 + (tid & 3) * 16;
    uint32_t bdst1 = smembase + STAGE_A + (tid >> 2) * AROW + (tid & 3) * 16;
    uint32_t bdst2 = bdst1 + 64 * AROW;

    auto issue = [&](int kt) {
        uint32_t so = (uint32_t)(kt & (ST - 1)) * STAGE_BYTES;
        const char* asrc = ((kt < 16) ? lsrc : rsrc) + ((kt * 64) & 1023);
        cp16(adst + so, asrc);
        cp16(bdst1 + so, bsrc1 + kt * 64);
        if (tid < 64) cp16(bdst2 + so, bsrc2 + kt * 64);
    };

    // fragment smem offsets (ldmatrix lane addressing)
    int wr = (warp >> 1) * 16, wc = (warp & 1) * 40;
    uint32_t aoff = smembase + (uint32_t)((wr + (lane & 7) + ((lane >> 3) & 1) * 8) * AROW
                                          + ((lane >> 4) & 1) * 16);
    uint32_t boff = smembase + STAGE_A + (uint32_t)(((wc + (lane & 7)) * AROW)
                                                    + ((lane >> 3) & 1) * 16);

    float acc[5][4];
    #pragma unroll
    for (int f = 0; f < 5; f++)
        #pragma unroll
        for (int q = 0; q < 4; q++) acc[f][q] = 0.0f;

    #pragma unroll
    for (int s = 0; s < ST - 1; s++) { issue(s); cp_commit(); }

    const int KT = D2 / BK;     // 32
    for (int kt = 0; kt < KT; kt++) {
        cp_wait<ST - 2>();
        __syncthreads();
        if (kt + ST - 1 < KT) issue(kt + ST - 1);
        cp_commit();
        uint32_t so = (uint32_t)(kt & (ST - 1)) * STAGE_BYTES;
        #pragma unroll
        for (int ks = 0; ks < 2; ks++) {
            uint32_t a0, a1, a2, a3;
            ldsm4(a0, a1, a2, a3, aoff + so + ks * 32);
            #pragma unroll
            for (int f = 0; f < 5; f++) {
                uint32_t b0, b1;
                ldsm2(b0, b1, boff + so + f * (8 * AROW) + ks * 32);
                mma16816(acc[f], a0, a1, a2, a3, b0, b1);
            }
        }
    }
    cp_wait<0>();
    __syncthreads();

    // reuse pipeline smem as the gate transpose buffer
    float (*Gs)[BN + 1] = (float (*)[BN + 1])smem;   // 64*81*4 = 20736 B
    int gp = lane >> 2, t4 = lane & 3;
    #pragma unroll
    for (int f = 0; f < 5; f++) {
        int c = wc + f * 8 + t4 * 2;
        Gs[wr + gp    ][c]     = acc[f][0];
        Gs[wr + gp    ][c + 1] = acc[f][1];
        Gs[wr + gp + 8][c]     = acc[f][2];
        Gs[wr + gp + 8][c + 1] = acc[f][3];
    }
    __syncthreads();

    // LSTM epilogue: 64 rows x 16 hidden units
    #pragma unroll
    for (int i = 0; i < 4; i++) {
        int e = tid + i * 256;
        int r = e >> 4, jl = e & 15;
        if (!s_valid[r]) continue;
        int b  = row0 + r;
        int jg = col0 / 5 + jl;
        int cb = jl * 5;
        float a  = Gs[r][cb + 0] + g_bias[col0 + cb + 0];
        float ii = Gs[r][cb + 1] + g_bias[col0 + cb + 1];
        float f1 = Gs[r][cb + 2] + g_bias[col0 + cb + 2];
        float f2 = Gs[r][cb + 3] + g_bias[col0 + cb + 3];
        float o  = Gs[r][cb + 4] + g_bias[col0 + cb + 4];
        float lc = s_lc[r][jg];
        float rc = s_rc[r][jg];
        float cc = tanhf(a) * sigm(ii) + sigm(f1) * lc + sigm(f2) * rc;
        float hh = sigm(o) * tanhf(cc);
        g_h[b][64 + kred][jg] = __float2half(hh);
        g_hf[b][kred][jg]     = hh;
        g_c[b][kred][jg]      = cc;
    }
}

// ---------------- final gather ----------------
__global__ void final_kernel(const float* __restrict__ buffers, float* __restrict__ out) {
    int i = blockIdx.x * blockDim.x + threadIdx.x;
    if (i >= BSZ * SZ) return;
    int b = i / SZ, j = i % SZ;
    int op = g_top[b];
    float v;
    if (op < 64)       v = buffers[(size_t)b * NLEAF * D2 + (size_t)op * D2 + j];
    else if (op < 128) v = g_hf[b][op - 64][j];
    else               v = 0.0f;
    out[i] = v;
}

// ---------------- launch ----------------
extern "C" void kernel_launch(void* const* d_in, const int* in_sizes, int n_in,
                              void* d_out, int out_size) {
    const float* buffers = (const float*)d_in[0];
    const int*   trans   = (const int*)d_in[1];
    const float* Wl      = (const float*)d_in[2];
    const float* Wr      = (const float*)d_in[3];
    const float* bl      = (const float*)d_in[4];
    float*       out     = (float*)d_out;

    int T  = in_sizes[1] / BSZ;
    int RL = (T + 1) / 2;
    if (RL > RMAX) RL = RMAX;

    init_zero_kernel<<<(BSZ * SZ + 255) / 256, 256>>>();
    leaf_convert_kernel<<<(BSZ * NLEAF * SZ + 255) / 256, 256>>>(buffers);
    convert_w_kernel<<<(GN * D2 + 255) / 256, 256>>>(Wl, Wr, bl);
    schedule_kernel<<<1, 256>>>(trans, T);

    dim3 grid(GN / BN, BSZ / BM);        // (32, 4) = 128 CTAs
    for (int k = 0; k < RL; ++k)
        step_kernel<<<grid, 256>>>(buffers, k);

    final_kernel<<<(BSZ * SZ + 255) / 256, 256>>>(buffers, out);
}

// round 3
// speedup vs baseline: 2.1120x; 1.0762x over previous
#include <cuda_runtime.h>
#include <cuda_fp16.h>
#include <cstdint>
#include <math.h>

#define BSZ   256
#define NLEAF 64
#define SZ    512
#define D2    1024
#define GN    2560
#define RMAX  64

#define BM 64
#define BN 80
#define NCTA 128

// smem layout (bytes)
#define ASTG   10240      // one A stage: 2 subtiles x (64 rows x 80B)
#define NSTAGE 3
#define ASMEM  (NSTAGE * ASTG)            // 30720
#define BROW   2064                        // B row stride (1024 halfs + 8 pad)
#define BOFFS  ASMEM                       // 30720
#define BBYTES (80 * BROW)                 // 165120
#define PTRO   (BOFFS + BBYTES)            // 195840
#define SMEM_TOTAL (PTRO + 2304)           // 198144

// ---------------- device scratch ----------------
__device__ __half   g_h[BSZ][129][SZ];     // 0..63 leaves, 64..127 results, 128 zero
__device__ float    g_c[BSZ][RMAX + 1][SZ];
__device__ float    g_hf[BSZ][RMAX][SZ];
__device__ __half   g_Wt[(size_t)GN * D2]; // [dc][k] gate-interleaved, transposed
__device__ float    g_bias[GN];
__device__ int      g_lop[BSZ * RMAX];
__device__ int      g_rop[BSZ * RMAX];
__device__ int      g_nred[BSZ];
__device__ int      g_top[BSZ];
__device__ unsigned g_bar;

__device__ __forceinline__ float sigm(float x) { return 1.0f / (1.0f + expf(-x)); }

// ---------------- PTX helpers ----------------
__device__ __forceinline__ void cp16(uint32_t sdst, const void* gsrc) {
    asm volatile("cp.async.cg.shared.global [%0], [%1], 16;\n" :: "r"(sdst), "l"(gsrc));
}
__device__ __forceinline__ void cp_commit() { asm volatile("cp.async.commit_group;\n" ::); }
template <int N> __device__ __forceinline__ void cp_wait() {
    asm volatile("cp.async.wait_group %0;\n" :: "n"(N));
}
__device__ __forceinline__ void ldsm4(uint32_t& r0, uint32_t& r1, uint32_t& r2, uint32_t& r3,
                                      uint32_t addr) {
    asm volatile("ldmatrix.sync.aligned.m8n8.x4.shared.b16 {%0,%1,%2,%3},[%4];\n"
                 : "=r"(r0), "=r"(r1), "=r"(r2), "=r"(r3) : "r"(addr));
}
__device__ __forceinline__ void ldsm2(uint32_t& r0, uint32_t& r1, uint32_t addr) {
    asm volatile("ldmatrix.sync.aligned.m8n8.x2.shared.b16 {%0,%1},[%2];\n"
                 : "=r"(r0), "=r"(r1) : "r"(addr));
}
__device__ __forceinline__ void mma16816(float* c, uint32_t a0, uint32_t a1, uint32_t a2,
                                         uint32_t a3, uint32_t b0, uint32_t b1) {
    asm volatile(
        "mma.sync.aligned.m16n8k16.row.col.f32.f16.f16.f32 "
        "{%0,%1,%2,%3},{%4,%5,%6,%7},{%8,%9},{%0,%1,%2,%3};\n"
        : "+f"(c[0]), "+f"(c[1]), "+f"(c[2]), "+f"(c[3])
        : "r"(a0), "r"(a1), "r"(a2), "r"(a3), "r"(b0), "r"(b1));
}

// ---------------- setup: leaves->fp16 (vec4) + zero slots ----------------
__global__ void setup_kernel(const float* __restrict__ buffers) {
    int bid = blockIdx.x, tid = threadIdx.x;
    if (bid < 8192) {                         // leaf convert, 4 elems/thread
        int i4 = (bid * 256 + tid) * 4;       // over 8,388,608
        int b = i4 >> 15, rem = i4 & 32767;
        int r = rem >> 9, j = rem & 511;
        float4 v = *(const float4*)(buffers + ((size_t)b << 16) + ((size_t)r << 10) + j);
        __half2 h0 = __floats2half2_rn(v.x, v.y);
        __half2 h1 = __floats2half2_rn(v.z, v.w);
        uint2 pk = make_uint2(*(uint32_t*)&h0, *(uint32_t*)&h1);
        *(uint2*)&g_h[b][r][j] = pk;
    } else {                                  // zero item slots
        int i = (bid - 8192) * 256 + tid;     // over 131072
        int b = i >> 9, j = i & 511;
        g_h[b][128][j] = __half(0.0f);
        g_c[b][RMAX][j] = 0.0f;
    }
}

// ---------------- weights: fp32 -> fp16, gate-interleave + transpose via smem ----------------
// dest g_Wt[dc][k], dc = 5*j+g, source Wl/Wr[k][g*512+j]
__global__ void convert_w_kernel(const float* __restrict__ Wl,
                                 const float* __restrict__ Wr,
                                 const float* __restrict__ bl) {
    __shared__ float tile[40][33];
    int tid = threadIdx.x;
    int dcb = blockIdx.x >> 5;               // 64 blocks of 40 dc
    int kb  = blockIdx.x & 31;               // 32 blocks of 32 k
    int dc0 = dcb * 40, k0 = kb * 32, j0 = dcb * 8;
    for (int e = tid; e < 1280; e += 256) {
        int jj = e & 7, g = (e >> 3) % 5, k = e / 40;
        int sc = g * SZ + j0 + jj;
        int kk = k0 + k;
        float v = (kk < SZ) ? Wl[(size_t)kk * GN + sc] : Wr[(size_t)(kk - SZ) * GN + sc];
        tile[5 * jj + g][k] = v;
    }
    __syncthreads();
    for (int e = tid; e < 1280; e += 256) {
        int kk = e & 31, dcl = e >> 5;
        g_Wt[((size_t)(dc0 + dcl) << 10) + k0 + kk] = __float2half(tile[dcl][kk]);
    }
    if (kb == 0 && tid < 40) {
        int dc = dc0 + tid, j = dc / 5, g = dc % 5;
        g_bias[dc] = bl[g * SZ + j];
    }
}

// ---------------- schedule: smem stacks, 8 blocks x 32 threads ----------------
__global__ void schedule_kernel(const int* __restrict__ trans, int T) {
    __shared__ int st[136][33];
    int lt = threadIdx.x;                    // 0..31
    int b = blockIdx.x * 32 + lt;
    for (int i = 0; i < 136; i++) st[i][lt] = 128;
    int ptr = 0, bptr = 0, nr = 0;
    for (int t = 0; t < T; t++) {
        int tr = trans[b * T + t];
        if (tr == 0) {                                   // SHIFT
            int n = (bptr < NLEAF - 1) ? bptr : (NLEAF - 1);
            int wp = ptr; if (wp < 0) wp = 0; if (wp > 130) wp = 130;
            st[wp][lt] = n;
            ptr++; bptr++;
        } else if (tr == 1) {                            // REDUCE
            int lp = ptr - 2; if (lp < 0) lp = 0;
            int rp = ptr - 1; if (rp < 0) rp = 0;
            if (nr < RMAX) {
                g_lop[(b << 6) + nr] = st[lp][lt];
                g_rop[(b << 6) + nr] = st[rp][lt];
                st[lp][lt] = 64 + nr;
                nr++;
            }
            ptr--;
        }
    }
    g_nred[b] = nr;
    int tp = ptr - 1; if (tp < 0) tp = 0; if (tp > 130) tp = 130;
    g_top[b] = st[tp][lt];
}

__global__ void reset_bar_kernel() { if (threadIdx.x == 0) g_bar = 0; }

// ---------------- persistent SPINN kernel ----------------
// grid (32, 4) = 128 CTAs, 256 threads; warp = kg*4 + wm*2 + wn; warp tile m32 x n40, k-split 2
__global__ __launch_bounds__(256, 1) void spinn_kernel(const float* __restrict__ buffers, int RL) {
    extern __shared__ __align__(16) char smem[];
    uint32_t sbase = (uint32_t)__cvta_generic_to_shared(smem);
    const __half** s_lh = (const __half**)(smem + PTRO);
    const __half** s_rh = (const __half**)(smem + PTRO + 512);
    const float**  s_lc = (const float**)(smem + PTRO + 1024);
    const float**  s_rc = (const float**)(smem + PTRO + 1536);
    int* s_valid = (int*)(smem + PTRO + 2048);

    int tid = threadIdx.x, warp = tid >> 5, lane = tid & 31;
    int kg = warp >> 2, wm = (warp >> 1) & 1, wn = warp & 1;
    int wr = wm * 32, wc = wn * 40;
    int row0 = blockIdx.y * BM, col0 = blockIdx.x * BN;

    // ---- load resident B tile (80 x 1024 fp16) ----
    for (int cch = tid; cch < 80 * 128; cch += 256) {
        int rrow = cch >> 7, cc = cch & 127;
        cp16(sbase + BOFFS + (uint32_t)(rrow * BROW + cc * 16),
             (const char*)g_Wt + (((size_t)(col0 + rrow)) << 11) + cc * 16);
    }
    cp_commit(); cp_wait<0>(); __syncthreads();

    // fixed per-thread addresses
    int arow = tid >> 2, achk = tid & 3;
    uint32_t adst = sbase + (uint32_t)(arow * 80 + achk * 16);
    uint32_t aoff0 = sbase + (uint32_t)((wr + (lane & 7) + ((lane >> 3) & 1) * 8) * 80
                                        + ((lane >> 4) & 1) * 16);
    uint32_t boff0 = sbase + BOFFS + (uint32_t)((wc + (lane & 7)) * BROW
                                                + ((lane >> 3) & 1) * 16);
    int gp = lane >> 2, t4 = lane & 3;

    for (int k = 0; k < RL; k++) {
        int v = 0;
        if (tid < 64) {
            int b = row0 + tid;
            int lop = g_lop[(b << 6) + k];
            int rop = g_rop[(b << 6) + k];
            s_lh[tid] = &g_h[b][lop][0];
            s_rh[tid] = &g_h[b][rop][0];
            s_lc[tid] = (lop < 64)  ? (buffers + ((size_t)b << 16) + ((size_t)lop << 10) + SZ)
                      : (lop < 128) ? &g_c[b][lop - 64][0] : &g_c[b][RMAX][0];
            s_rc[tid] = (rop < 64)  ? (buffers + ((size_t)b << 16) + ((size_t)rop << 10) + SZ)
                      : (rop < 128) ? &g_c[b][rop - 64][0] : &g_c[b][RMAX][0];
            v = s_valid[tid] = (k < g_nred[b]) ? 1 : 0;
        }
        if (__syncthreads_or(v)) {
            const char* lsrc = (const char*)s_lh[arow] + achk * 16;
            const char* rsrc = (const char*)s_rh[arow] + achk * 16;

            auto issueA = [&](int it) {
                uint32_t so = (uint32_t)(it % NSTAGE) * ASTG;
                #pragma unroll
                for (int j = 0; j < 2; j++) {
                    int k0 = it * 64 + j * 32;
                    const char* src = ((k0 < SZ) ? lsrc : rsrc) + ((k0 & 511) << 1);
                    cp16(adst + so + j * 5120u, src);
                }
            };

            float acc[2][5][4];
            #pragma unroll
            for (int s = 0; s < 2; s++)
                #pragma unroll
                for (int f = 0; f < 5; f++)
                    #pragma unroll
                    for (int q = 0; q < 4; q++) acc[s][f][q] = 0.0f;

            issueA(0); cp_commit();
            issueA(1); cp_commit();

            for (int it = 0; it < 16; it++) {
                cp_wait<1>();
                __syncthreads();
                if (it + 2 < 16) issueA(it + 2);
                cp_commit();
                uint32_t so  = (uint32_t)(it % NSTAGE) * ASTG + (uint32_t)kg * 5120u;
                uint32_t kbB = (uint32_t)(it * 128 + kg * 64);
                #pragma unroll
                for (int ks = 0; ks < 2; ks++) {
                    uint32_t aA[4], aB[4];
                    ldsm4(aA[0], aA[1], aA[2], aA[3], aoff0 + so + ks * 32);
                    ldsm4(aB[0], aB[1], aB[2], aB[3], aoff0 + so + 1280 + ks * 32);
                    #pragma unroll
                    for (int f = 0; f < 5; f++) {
                        uint32_t b0, b1;
                        ldsm2(b0, b1, boff0 + f * (8 * BROW) + kbB + ks * 32);
                        mma16816(acc[0][f], aA[0], aA[1], aA[2], aA[3], b0, b1);
                        mma16816(acc[1][f], aB[0], aB[1], aB[2], aB[3], b0, b1);
                    }
                }
            }
            cp_wait<0>();
            __syncthreads();

            // k-split reduction + gate transpose in (reused) A-stage smem
            float (*Gs)[BN + 1] = (float (*)[BN + 1])smem;
            if (kg == 1) {
                #pragma unroll
                for (int s = 0; s < 2; s++)
                    #pragma unroll
                    for (int f = 0; f < 5; f++) {
                        int rr = wr + s * 16 + gp, cc = wc + f * 8 + t4 * 2;
                        Gs[rr][cc]         = acc[s][f][0];
                        Gs[rr][cc + 1]     = acc[s][f][1];
                        Gs[rr + 8][cc]     = acc[s][f][2];
                        Gs[rr + 8][cc + 1] = acc[s][f][3];
                    }
            }
            __syncthreads();
            if (kg == 0) {
                #pragma unroll
                for (int s = 0; s < 2; s++)
                    #pragma unroll
                    for (int f = 0; f < 5; f++) {
                        int rr = wr + s * 16 + gp, cc = wc + f * 8 + t4 * 2;
                        Gs[rr][cc]         += acc[s][f][0];
                        Gs[rr][cc + 1]     += acc[s][f][1];
                        Gs[rr + 8][cc]     += acc[s][f][2];
                        Gs[rr + 8][cc + 1] += acc[s][f][3];
                    }
            }
            __syncthreads();

            // LSTM epilogue: 64 rows x 16 hidden units
            #pragma unroll
            for (int i = 0; i < 4; i++) {
                int e = tid + i * 256;
                int r = e >> 4, jl = e & 15;
                if (s_valid[r]) {
                    int b  = row0 + r;
                    int jg = (col0 / 5) + jl;
                    int cb = jl * 5;
                    float a  = Gs[r][cb + 0] + g_bias[col0 + cb + 0];
                    float ii = Gs[r][cb + 1] + g_bias[col0 + cb + 1];
                    float f1 = Gs[r][cb + 2] + g_bias[col0 + cb + 2];
                    float f2 = Gs[r][cb + 3] + g_bias[col0 + cb + 3];
                    float o  = Gs[r][cb + 4] + g_bias[col0 + cb + 4];
                    float lc = s_lc[r][jg];
                    float rc = s_rc[r][jg];
                    float cc = tanhf(a) * sigm(ii) + sigm(f1) * lc + sigm(f2) * rc;
                    float hh = sigm(o) * tanhf(cc);
                    g_h[b][64 + k][jg] = __float2half(hh);
                    g_hf[b][k][jg]     = hh;
                    g_c[b][k][jg]      = cc;
                }
            }
        }

        // ---- grid-wide barrier ----
        __syncthreads();
        __threadfence();
        if (tid == 0) {
            atomicAdd(&g_bar, 1u);
            unsigned tgt = (unsigned)(NCTA * (k + 1));
            while (*((volatile unsigned*)&g_bar) < tgt) { }
        }
        __syncthreads();
        __threadfence();
    }
}

// ---------------- final gather ----------------
__global__ void final_kernel(const float* __restrict__ buffers, float* __restrict__ out) {
    int i = blockIdx.x * blockDim.x + threadIdx.x;
    if (i >= BSZ * SZ) return;
    int b = i / SZ, j = i % SZ;
    int op = g_top[b];
    float v;
    if (op < 64)       v = buffers[((size_t)b << 16) + ((size_t)op << 10) + j];
    else if (op < 128) v = g_hf[b][op - 64][j];
    else               v = 0.0f;
    out[i] = v;
}

// ---------------- launch ----------------
extern "C" void kernel_launch(void* const* d_in, const int* in_sizes, int n_in,
                              void* d_out, int out_size) {
    const float* buffers = (const float*)d_in[0];
    const int*   trans   = (const int*)d_in[1];
    const float* Wl      = (const float*)d_in[2];
    const float* Wr      = (const float*)d_in[3];
    const float* bl      = (const float*)d_in[4];
    float*       out     = (float*)d_out;

    int T  = in_sizes[1] / BSZ;
    int RL = (T + 1) / 2;
    if (RL > RMAX) RL = RMAX;

    static int attr_done = 0;
    if (!attr_done) {
        cudaFuncSetAttribute(spinn_kernel, cudaFuncAttributeMaxDynamicSharedMemorySize,
                             SMEM_TOTAL);
        attr_done = 1;
    }

    schedule_kernel<<<8, 32>>>(trans, T);
    setup_kernel<<<8192 + 512, 256>>>(buffers);
    convert_w_kernel<<<2048, 256>>>(Wl, Wr, bl);
    reset_bar_kernel<<<1, 32>>>();

    dim3 grid(GN / BN, BSZ / BM);   // (32, 4) = 128 CTAs
    spinn_kernel<<<grid, 256, SMEM_TOTAL>>>(buffers, RL);

    final_kernel<<<(BSZ * SZ + 255) / 256, 256>>>(buffers, out);
}